// round 1
// baseline (speedup 1.0000x reference)
#include <cuda_runtime.h>
#include <float.h>

// Problem constants (from reference: B=4096, N=2048, 3 (o,t) pairs)
#define BB 4096
#define NN 2048
#define NPAIR 3
#define ROW_THREADS 256

// Scratch for per-row weighted contributions (deterministic two-pass reduce;
// no atomics -> bitwise-identical output every call).
__device__ float g_partials[NPAIR * BB];

__global__ __launch_bounds__(ROW_THREADS)
void wnrmse_row_kernel(const float* __restrict__ o1, const float* __restrict__ t1,
                       const float* __restrict__ o2, const float* __restrict__ t2,
                       const float* __restrict__ o3, const float* __restrict__ t3) {
    const int b = blockIdx.x;   // batch row
    const int p = blockIdx.y;   // pair index

    const float* o = (p == 0) ? o1 : ((p == 1) ? o2 : o3);
    const float* t = (p == 0) ? t1 : ((p == 1) ? t2 : t3);

    const float4* __restrict__ o4 = reinterpret_cast<const float4*>(o + (size_t)b * NN);
    const float4* __restrict__ t4 = reinterpret_cast<const float4*>(t + (size_t)b * NN);

    const int tid = threadIdx.x;

    float ssq  = 0.0f;
    float tmax = -FLT_MAX;
    float tmin =  FLT_MAX;

    // 2048 floats = 512 float4 per tensor; 256 threads -> 2 float4 each.
    // Front-batch all 4 loads for MLP.
    float4 ov0 = o4[tid];
    float4 tv0 = t4[tid];
    float4 ov1 = o4[tid + ROW_THREADS];
    float4 tv1 = t4[tid + ROW_THREADS];

    {
        float d;
        d = ov0.x - tv0.x; ssq = fmaf(d, d, ssq); tmax = fmaxf(tmax, tv0.x); tmin = fminf(tmin, tv0.x);
        d = ov0.y - tv0.y; ssq = fmaf(d, d, ssq); tmax = fmaxf(tmax, tv0.y); tmin = fminf(tmin, tv0.y);
        d = ov0.z - tv0.z; ssq = fmaf(d, d, ssq); tmax = fmaxf(tmax, tv0.z); tmin = fminf(tmin, tv0.z);
        d = ov0.w - tv0.w; ssq = fmaf(d, d, ssq); tmax = fmaxf(tmax, tv0.w); tmin = fminf(tmin, tv0.w);
        d = ov1.x - tv1.x; ssq = fmaf(d, d, ssq); tmax = fmaxf(tmax, tv1.x); tmin = fminf(tmin, tv1.x);
        d = ov1.y - tv1.y; ssq = fmaf(d, d, ssq); tmax = fmaxf(tmax, tv1.y); tmin = fminf(tmin, tv1.y);
        d = ov1.z - tv1.z; ssq = fmaf(d, d, ssq); tmax = fmaxf(tmax, tv1.z); tmin = fminf(tmin, tv1.z);
        d = ov1.w - tv1.w; ssq = fmaf(d, d, ssq); tmax = fmaxf(tmax, tv1.w); tmin = fminf(tmin, tv1.w);
    }

    // Intra-warp reduce
    #pragma unroll
    for (int off = 16; off > 0; off >>= 1) {
        ssq  += __shfl_xor_sync(0xFFFFFFFFu, ssq,  off);
        tmax  = fmaxf(tmax, __shfl_xor_sync(0xFFFFFFFFu, tmax, off));
        tmin  = fminf(tmin, __shfl_xor_sync(0xFFFFFFFFu, tmin, off));
    }

    // Cross-warp reduce (8 warps)
    __shared__ float s_ssq[8], s_max[8], s_min[8];
    const int w = tid >> 5, l = tid & 31;
    if (l == 0) { s_ssq[w] = ssq; s_max[w] = tmax; s_min[w] = tmin; }
    __syncthreads();

    if (w == 0) {
        float a  = (l < 8) ? s_ssq[l] : 0.0f;
        float mx = (l < 8) ? s_max[l] : -FLT_MAX;
        float mn = (l < 8) ? s_min[l] :  FLT_MAX;
        #pragma unroll
        for (int off = 4; off > 0; off >>= 1) {
            a  += __shfl_xor_sync(0xFFFFFFFFu, a,  off);
            mx  = fmaxf(mx, __shfl_xor_sync(0xFFFFFFFFu, mx, off));
            mn  = fminf(mn, __shfl_xor_sync(0xFFFFFFFFu, mn, off));
        }
        if (l == 0) {
            const float wgt = (p == 0) ? 0.5f : 0.25f;
            // rmse / range, weighted
            g_partials[p * BB + b] = wgt * sqrtf(a * (1.0f / NN)) / (mx - mn);
        }
    }
}

__global__ __launch_bounds__(1024)
void wnrmse_reduce_kernel(float* __restrict__ out) {
    const int tid = threadIdx.x;
    float s = 0.0f;
    #pragma unroll
    for (int i = tid; i < NPAIR * BB; i += 1024) s += g_partials[i];

    #pragma unroll
    for (int off = 16; off > 0; off >>= 1)
        s += __shfl_xor_sync(0xFFFFFFFFu, s, off);

    __shared__ float s_part[32];
    const int w = tid >> 5, l = tid & 31;
    if (l == 0) s_part[w] = s;
    __syncthreads();
    if (w == 0) {
        float a = s_part[l];   // exactly 32 warps
        #pragma unroll
        for (int off = 16; off > 0; off >>= 1)
            a += __shfl_xor_sync(0xFFFFFFFFu, a, off);
        if (l == 0) out[0] = a * (1.0f / BB);
    }
}

extern "C" void kernel_launch(void* const* d_in, const int* in_sizes, int n_in,
                              void* d_out, int out_size) {
    const float* o1 = (const float*)d_in[0];
    const float* t1 = (const float*)d_in[1];
    const float* o2 = (const float*)d_in[2];
    const float* t2 = (const float*)d_in[3];
    const float* o3 = (const float*)d_in[4];
    const float* t3 = (const float*)d_in[5];
    float* out = (float*)d_out;

    dim3 grid(BB, NPAIR);
    wnrmse_row_kernel<<<grid, ROW_THREADS>>>(o1, t1, o2, t2, o3, t3);
    wnrmse_reduce_kernel<<<1, 1024>>>(out);
}